// round 10
// baseline (speedup 1.0000x reference)
#include <cuda_runtime.h>
#include <cuda_bf16.h>
#include <math.h>

#define N_   8192
#define D_   2048
#define P_   512
#define NB_  16          // k0 partition blocks (512 samples each)
#define EPSF 1e-12f
#define S_   8           // k1 bulk-copy ring depth (8 x 8KB = 64KB dynamic smem)

// ---------------- scratch (device globals; no allocation allowed) ----------
__device__ int   g_count[P_];
__device__ int   g_offset[P_];
__device__ int   g_members[N_];
__device__ int   g_pc[NB_][P_];       // per-partition class histograms
__device__ __nv_bfloat16 g_cbf[3][P_][D_];   // unit centers, bf16
__device__ float g_expsum[3][P_];     // per-row sum of exp(2*dot)
__device__ float g_sumnorm;           // sum ||s_c|| over all (m, c)
__device__ float g_sumdiag;           // sum of diagonal dots over all (p, i)

// ---------------- helpers --------------------------------------------------
__device__ __forceinline__ float warpSum(float v) {
#pragma unroll
    for (int o = 16; o; o >>= 1) v += __shfl_xor_sync(0xffffffffu, v, o);
    return v;
}
__device__ __forceinline__ unsigned bfpack(float lo, float hi) {
    unsigned a = (unsigned)__bfloat16_as_ushort(__float2bfloat16_rn(lo));
    unsigned b = (unsigned)__bfloat16_as_ushort(__float2bfloat16_rn(hi));
    return a | (b << 16);
}
__device__ __forceinline__ void mbar_init(unsigned mbar, unsigned count) {
    asm volatile("mbarrier.init.shared.b64 [%0], %1;" :: "r"(mbar), "r"(count) : "memory");
}
__device__ __forceinline__ void mbar_expect_tx(unsigned mbar, unsigned tx) {
    asm volatile("mbarrier.arrive.expect_tx.shared.b64 _, [%0], %1;" :: "r"(mbar), "r"(tx) : "memory");
}
__device__ __forceinline__ void mbar_wait(unsigned mbar, unsigned parity) {
    asm volatile(
        "{\n\t"
        ".reg .pred P1;\n\t"
        "WAIT_LOOP_%=:\n\t"
        "mbarrier.try_wait.parity.acquire.cta.shared::cta.b64 P1, [%0], %1, 0x989680;\n\t"
        "@P1 bra.uni WAIT_DONE_%=;\n\t"
        "bra.uni WAIT_LOOP_%=;\n\t"
        "WAIT_DONE_%=:\n\t"
        "}"
        :: "r"(mbar), "r"(parity) : "memory");
}
__device__ __forceinline__ void bulk_cp(void* dst, const void* src, unsigned bytes, unsigned mbar) {
    unsigned d = (unsigned)__cvta_generic_to_shared(dst);
    asm volatile(
        "cp.async.bulk.shared::cta.global.mbarrier::complete_tx::bytes [%0], [%1], %2, [%3];"
        :: "r"(d), "l"(src), "r"(bytes), "r"(mbar) : "memory");
}
__device__ __forceinline__ void cpa16(void* dst, const void* src) {
    unsigned d = (unsigned)__cvta_generic_to_shared(dst);
    asm volatile("cp.async.cg.shared.global [%0], [%1], 16;\n" :: "r"(d), "l"(src));
}
__device__ __forceinline__ void cpa_commit() {
    asm volatile("cp.async.commit_group;\n" ::: "memory");
}
template <int Npend>
__device__ __forceinline__ void cpa_wait() {
    asm volatile("cp.async.wait_group %0;\n" :: "n"(Npend) : "memory");
}

// ---------------- kernel 0a: per-partition histogram + zero accumulators ---
__global__ void __launch_bounds__(512) k0a_hist(const int* __restrict__ label) {
    __shared__ int h[P_];
    int t = threadIdx.x, b = blockIdx.x;
    h[t] = 0;
    __syncthreads();
    int l = __ldg(&label[b * 512 + t]);
    atomicAdd(&h[l], 1);
    __syncthreads();
    g_pc[b][t] = h[t];
    if (b == 0) {
        g_expsum[0][t] = 0.f; g_expsum[1][t] = 0.f; g_expsum[2][t] = 0.f;
        if (t == 0) { g_sumnorm = 0.f; g_sumdiag = 0.f; }
    }
}

// ---------------- kernel 0b: redundant scan + parallel fill (grid NB_) -----
__global__ void __launch_bounds__(512) k0b_fill(const int* __restrict__ label) {
    __shared__ int cur[P_];
    __shared__ int ws[16];
    int t = threadIdx.x, b = blockIdx.x, lane = t & 31, w = t >> 5;

    int pref = 0, tot = 0;
#pragma unroll
    for (int bb = 0; bb < NB_; bb++) {
        int v = g_pc[bb][t];
        if (bb < b) pref += v;
        tot += v;
    }
    int inc = tot;
#pragma unroll
    for (int o = 1; o < 32; o <<= 1) {
        int v = __shfl_up_sync(0xffffffffu, inc, o);
        if (lane >= o) inc += v;
    }
    if (lane == 31) ws[w] = inc;
    __syncthreads();
    if (t < 32) {
        int v = (t < 16) ? ws[t] : 0;
        int s = v;
#pragma unroll
        for (int o = 1; o < 32; o <<= 1) {
            int u = __shfl_up_sync(0xffffffffu, s, o);
            if (lane >= o) s += u;
        }
        if (t < 16) ws[t] = s - v;
    }
    __syncthreads();
    int exc = ws[w] + inc - tot;          // exclusive class prefix
    if (b == 0) { g_count[t] = tot; g_offset[t] = exc; }
    cur[t] = exc + pref;                  // this partition's write base
    __syncthreads();
    int i = b * 512 + t;
    int c = __ldg(&label[i]);
    int pos = atomicAdd(&cur[c], 1);
    g_members[pos] = i;
}

// ---------------- kernel 1: centers via cp.async.bulk ring ------------------
__global__ void __launch_bounds__(256) k1_centers(const float* __restrict__ f0,
                                                  const float* __restrict__ f1,
                                                  const float* __restrict__ f2) {
    extern __shared__ __align__(16) float stg[];   // [S_][D_]
    __shared__ __align__(8) unsigned long long mbar[S_];
    __shared__ float wred[2][8];
    __shared__ int rows_s[32];

    int c = blockIdx.x, m = blockIdx.y;
    const float* f = (m == 0) ? f0 : ((m == 1) ? f1 : f2);
    int off = g_offset[c];
    int K   = g_count[c];
    int t   = threadIdx.x, w = t >> 5, lane = t & 31;

    if (t < 32 && t < K) rows_s[t] = __ldg(&g_members[off + t]);
    if (t == 0) {
#pragma unroll
        for (int s = 0; s < S_; s++)
            mbar_init((unsigned)__cvta_generic_to_shared(&mbar[s]), 1);
        asm volatile("fence.proxy.async;" ::: "memory");
    }
    __syncthreads();

    if (t == 0) {
#pragma unroll
        for (int s = 0; s < S_; s++) {
            if (s < K) {
                unsigned mb = (unsigned)__cvta_generic_to_shared(&mbar[s]);
                mbar_expect_tx(mb, D_ * 4);
                bulk_cp(&stg[s * D_], f + (size_t)rows_s[s] * D_, D_ * 4, mb);
            }
        }
    }

    float a0 = 0.f, a1 = 0.f, a2 = 0.f, a3 = 0.f;
    float a4 = 0.f, a5 = 0.f, a6 = 0.f, a7 = 0.f;

    for (int k = 0; k < K; k++) {
        int sb = k & (S_ - 1);
        unsigned mb = (unsigned)__cvta_generic_to_shared(&mbar[sb]);
        mbar_wait(mb, (unsigned)((k >> 3) & 1));
        float4 x = *(const float4*)&stg[sb * D_ + t * 4];
        float4 y = *(const float4*)&stg[sb * D_ + 1024 + t * 4];
        float ss = warpSum(x.x * x.x + x.y * x.y + x.z * x.z + x.w * x.w
                         + y.x * y.x + y.y * y.y + y.z * y.z + y.w * y.w);
        if (lane == 0) wred[k & 1][w] = ss;
        __syncthreads();               // reduction ready AND stage consumed
        if (t == 0 && k + S_ < K) {    // re-arm the just-freed stage
            int idx = k + S_;
            int row = (idx < 32) ? rows_s[idx] : __ldg(&g_members[off + idx]);
            mbar_expect_tx(mb, D_ * 4);
            bulk_cp(&stg[sb * D_], f + (size_t)row * D_, D_ * 4, mb);
        }
        float tot = wred[k & 1][0] + wred[k & 1][1] + wred[k & 1][2] + wred[k & 1][3]
                  + wred[k & 1][4] + wred[k & 1][5] + wred[k & 1][6] + wred[k & 1][7];
        float inv = rsqrtf(fmaxf(tot, 1e-24f));
        a0 += x.x * inv; a1 += x.y * inv; a2 += x.z * inv; a3 += x.w * inv;
        a4 += y.x * inv; a5 += y.y * inv; a6 += y.z * inv; a7 += y.w * inv;
    }

    float ss2 = a0 * a0 + a1 * a1 + a2 * a2 + a3 * a3
              + a4 * a4 + a5 * a5 + a6 * a6 + a7 * a7;
    ss2 = warpSum(ss2);
    __syncthreads();
    if (lane == 0) wred[0][w] = ss2;
    __syncthreads();
    float tot2 = wred[0][0] + wred[0][1] + wred[0][2] + wred[0][3]
               + wred[0][4] + wred[0][5] + wred[0][6] + wred[0][7];
    float nrm  = sqrtf(tot2);
    float inv2 = 1.f / fmaxf(nrm, EPSF);

    __nv_bfloat16* cb = &g_cbf[m][c][0];
    uint2 u0, u1;
    u0.x = bfpack(a0 * inv2, a1 * inv2); u0.y = bfpack(a2 * inv2, a3 * inv2);
    u1.x = bfpack(a4 * inv2, a5 * inv2); u1.y = bfpack(a6 * inv2, a7 * inv2);
    *(uint2*)(cb + 4 * t)         = u0;
    *(uint2*)(cb + 4 * (t + 256)) = u1;
    if (t == 0) atomicAdd(&g_sumnorm, nrm);
}

// ---------------- kernel 2: bf16 mma GEMM, 64x64 tiles, cp.async 2-stage ---
// grid (8, 8, 3) = 192 blocks, block 128 (4 warps 2x2, warp tile 32x32).
// Double-buffered smem (4 x 8KB dynamic): wait -> sync -> prefetch -> mma.
// Operands (12MB total for 3 GEMMs) are L2-resident.
#define KC_ 64
__device__ __forceinline__ unsigned sw_off(int row, int g) {
    return (unsigned)(row * 128 + ((g ^ (row & 7)) << 4));
}

__global__ void __launch_bounds__(128) k2_gemm() {
    extern __shared__ __align__(16) unsigned char sm2[];
    // layout: As[0]@0, As[1]@8K, Bs[0]@16K, Bs[1]@24K
    int p  = blockIdx.z;
    int pa = (p == 2) ? 1 : 0;
    int pb = (p == 0) ? 1 : 2;
    const __nv_bfloat16* A = &g_cbf[pa][0][0];
    const __nv_bfloat16* B = &g_cbf[pb][0][0];

    int t = threadIdx.x, lane = t & 31, warp = t >> 5;
    int wr = warp >> 1, wc = warp & 1;
    int brow = blockIdx.y * 64, bcol = blockIdx.x * 64;

    float acc[2][4][4];
#pragma unroll
    for (int mt = 0; mt < 2; mt++)
#pragma unroll
        for (int nt = 0; nt < 4; nt++)
#pragma unroll
            for (int e = 0; e < 4; e++) acc[mt][nt][e] = 0.f;

    int rsel = lane & 15, gsel = lane >> 4;
    int lrow = t >> 1, lg = (t & 1) << 2;   // loader: 128 threads x 2 cp.async cover 64x8 granules

    // prologue: chunk 0 -> buffer 0
#pragma unroll
    for (int j = 0; j < 2; j++) {
        int row = lrow, g = lg + j * 2;     // g in {0..7}: each thread does g, g+2 pattern
        cpa16(sm2 + sw_off(row, g),         A + (size_t)(brow + row) * D_ + g * 8);
        cpa16(sm2 + 16384 + sw_off(row, g), B + (size_t)(bcol + row) * D_ + g * 8);
        cpa16(sm2 + sw_off(row, g + 1),         A + (size_t)(brow + row) * D_ + (g + 1) * 8);
        cpa16(sm2 + 16384 + sw_off(row, g + 1), B + (size_t)(bcol + row) * D_ + (g + 1) * 8);
    }
    cpa_commit();

    for (int kc = 0; kc < D_ / KC_; kc++) {
        int buf = kc & 1;
        unsigned ab = (unsigned)__cvta_generic_to_shared(sm2) + buf * 8192u;
        unsigned bb = (unsigned)__cvta_generic_to_shared(sm2) + 16384u + buf * 8192u;
        cpa_wait<0>();          // chunk kc landed
        __syncthreads();        // all threads done reading buf^1 (iter kc-1)

        if (kc + 1 < D_ / KC_) {  // prefetch chunk kc+1 into the other buffer
            int nb = buf ^ 1;
            int co = (kc + 1) * KC_;
            unsigned char* ad = sm2 + nb * 8192;
            unsigned char* bd = sm2 + 16384 + nb * 8192;
#pragma unroll
            for (int j = 0; j < 2; j++) {
                int row = lrow, g = lg + j * 2;
                cpa16(ad + sw_off(row, g),     A + (size_t)(brow + row) * D_ + co + g * 8);
                cpa16(bd + sw_off(row, g),     B + (size_t)(bcol + row) * D_ + co + g * 8);
                cpa16(ad + sw_off(row, g + 1), A + (size_t)(brow + row) * D_ + co + (g + 1) * 8);
                cpa16(bd + sw_off(row, g + 1), B + (size_t)(bcol + row) * D_ + co + (g + 1) * 8);
            }
            cpa_commit();
        } else {
            cpa_commit();       // keep group count consistent
        }

#pragma unroll
        for (int kh = 0; kh < 4; kh++) {
            unsigned af[2][4], bfr[2][4];
#pragma unroll
            for (int mt = 0; mt < 2; mt++) {
                unsigned ad = ab + sw_off(wr * 32 + mt * 16 + rsel, kh * 2 + gsel);
                asm volatile("ldmatrix.sync.aligned.m8n8.x4.shared.b16 {%0,%1,%2,%3}, [%4];"
                             : "=r"(af[mt][0]), "=r"(af[mt][1]), "=r"(af[mt][2]), "=r"(af[mt][3])
                             : "r"(ad));
            }
#pragma unroll
            for (int np = 0; np < 2; np++) {
                unsigned bd = bb + sw_off(wc * 32 + np * 16 + rsel, kh * 2 + gsel);
                asm volatile("ldmatrix.sync.aligned.m8n8.x4.shared.b16 {%0,%1,%2,%3}, [%4];"
                             : "=r"(bfr[np][0]), "=r"(bfr[np][1]), "=r"(bfr[np][2]), "=r"(bfr[np][3])
                             : "r"(bd));
            }
#pragma unroll
            for (int mt = 0; mt < 2; mt++)
#pragma unroll
                for (int nt = 0; nt < 4; nt++) {
                    int np = nt >> 1, s = nt & 1;
                    asm volatile(
                        "mma.sync.aligned.m16n8k16.row.col.f32.bf16.bf16.f32 "
                        "{%0,%1,%2,%3},{%4,%5,%6,%7},{%8,%9},{%0,%1,%2,%3};"
                        : "+f"(acc[mt][nt][0]), "+f"(acc[mt][nt][1]),
                          "+f"(acc[mt][nt][2]), "+f"(acc[mt][nt][3])
                        : "r"(af[mt][0]), "r"(af[mt][1]), "r"(af[mt][2]), "r"(af[mt][3]),
                          "r"(bfr[np][0 + s]), "r"(bfr[np][2 + s]));
                }
        }
    }

    // ---- fused epilogue: per-row sum of exp(2*dot) + diagonal dots ----
#pragma unroll
    for (int mt = 0; mt < 2; mt++) {
        float s0 = 0.f, s1 = 0.f;
#pragma unroll
        for (int nt = 0; nt < 4; nt++) {
            s0 += __expf(2.f * acc[mt][nt][0]) + __expf(2.f * acc[mt][nt][1]);
            s1 += __expf(2.f * acc[mt][nt][2]) + __expf(2.f * acc[mt][nt][3]);
        }
        s0 += __shfl_xor_sync(0xffffffffu, s0, 1);
        s0 += __shfl_xor_sync(0xffffffffu, s0, 2);
        s1 += __shfl_xor_sync(0xffffffffu, s1, 1);
        s1 += __shfl_xor_sync(0xffffffffu, s1, 2);
        if ((lane & 3) == 0) {
            int r0 = brow + wr * 32 + mt * 16 + (lane >> 2);
            atomicAdd(&g_expsum[p][r0],     s0);
            atomicAdd(&g_expsum[p][r0 + 8], s1);
        }
    }
    if (brow == bcol) {
        float dsum = 0.f;
#pragma unroll
        for (int mt = 0; mt < 2; mt++)
#pragma unroll
            for (int nt = 0; nt < 4; nt++) {
                int gr = brow + wr * 32 + mt * 16 + (lane >> 2);
                int gc = bcol + wc * 32 + nt * 8 + (lane & 3) * 2;
                if (gr == gc)         dsum += acc[mt][nt][0];
                if (gc + 1 == gr)     dsum += acc[mt][nt][1];
                if (gr + 8 == gc)     dsum += acc[mt][nt][2];
                if (gc + 1 == gr + 8) dsum += acc[mt][nt][3];
            }
        if (dsum != 0.f) atomicAdd(&g_sumdiag, dsum);
    }
}

// ---------------- kernel 3: final scalar (1 block, 512) --------------------
__global__ void __launch_bounds__(512) k3_final(float* __restrict__ out) {
    int t = threadIdx.x;
    float L = __logf(g_expsum[0][t]) + __logf(g_expsum[1][t]) + __logf(g_expsum[2][t]);
    __shared__ float w1[16];
    L = warpSum(L);
    if ((t & 31) == 0) w1[t >> 5] = L;
    __syncthreads();
    if (t == 0) {
        float S = 0.f;
        for (int i = 0; i < 16; i++) S += w1[i];
        // loss_intra = 6 - (2/N)*sum||s||
        // loss_inter = (sum log S_r - 2*sum diag) / P
        out[0] = 6.f - g_sumnorm / 4096.f + (S - 2.f * g_sumdiag) / 512.f;
    }
}

// ---------------- launch ----------------------------------------------------
extern "C" void kernel_launch(void* const* d_in, const int* in_sizes, int n_in,
                              void* d_out, int out_size) {
    const float* fv    = (const float*)d_in[0];
    const float* fa    = (const float*)d_in[1];
    const float* fr    = (const float*)d_in[2];
    const int*   label = (const int*)d_in[3];
    (void)in_sizes; (void)n_in; (void)out_size;

    cudaFuncSetAttribute(k1_centers, cudaFuncAttributeMaxDynamicSharedMemorySize,
                         S_ * D_ * (int)sizeof(float));

    k0a_hist<<<NB_, 512>>>(label);
    k0b_fill<<<NB_, 512>>>(label);
    k1_centers<<<dim3(P_, 3), 256, S_ * D_ * sizeof(float)>>>(fv, fa, fr);
    k2_gemm<<<dim3(8, 8, 3), 128, 32768>>>();
    k3_final<<<1, 512>>>((float*)d_out);
}

// round 12
// speedup vs baseline: 1.1814x; 1.1814x over previous
#include <cuda_runtime.h>
#include <cuda_bf16.h>
#include <math.h>

#define N_   8192
#define D_   2048
#define P_   512
#define NB_  16          // k0 partition blocks (512 samples each)
#define EPSF 1e-12f
#define S_   4           // k1 LDGSTS ring depth (4 x 8KB static smem)

// ---------------- scratch (device globals; no allocation allowed) ----------
__device__ int   g_count[P_];
__device__ int   g_offset[P_];
__device__ int   g_members[N_];
__device__ int   g_pc[NB_][P_];              // per-partition class histograms
__device__ __nv_bfloat16 g_cbf[3][P_][D_];   // unit centers, bf16
__device__ float g_part[3][4][P_][P_];       // split-K partial dot planes (12MB)
__device__ float g_rowloss[3 * P_];
__device__ float g_sumnorm;                  // sum ||s_c|| over all (m, c)

// ---------------- helpers --------------------------------------------------
__device__ __forceinline__ float warpSum(float v) {
#pragma unroll
    for (int o = 16; o; o >>= 1) v += __shfl_xor_sync(0xffffffffu, v, o);
    return v;
}
__device__ __forceinline__ unsigned bfpack(float lo, float hi) {
    unsigned a = (unsigned)__bfloat16_as_ushort(__float2bfloat16_rn(lo));
    unsigned b = (unsigned)__bfloat16_as_ushort(__float2bfloat16_rn(hi));
    return a | (b << 16);
}
__device__ __forceinline__ float dot8(const float4& x, const float4& y) {
    return x.x * x.x + x.y * x.y + x.z * x.z + x.w * x.w
         + y.x * y.x + y.y * y.y + y.z * y.z + y.w * y.w;
}
__device__ __forceinline__ void cpa16(void* dst, const void* src) {
    unsigned d = (unsigned)__cvta_generic_to_shared(dst);
    asm volatile("cp.async.cg.shared.global [%0], [%1], 16;\n" :: "r"(d), "l"(src));
}
__device__ __forceinline__ void cpa_commit() {
    asm volatile("cp.async.commit_group;\n" ::: "memory");
}
template <int Npend>
__device__ __forceinline__ void cpa_wait() {
    asm volatile("cp.async.wait_group %0;\n" :: "n"(Npend) : "memory");
}

// ---------------- kernel 0a: per-partition histogram + zero sumnorm --------
__global__ void __launch_bounds__(512) k0a_hist(const int* __restrict__ label) {
    __shared__ int h[P_];
    int t = threadIdx.x, b = blockIdx.x;
    h[t] = 0;
    __syncthreads();
    int l = __ldg(&label[b * 512 + t]);
    atomicAdd(&h[l], 1);
    __syncthreads();
    g_pc[b][t] = h[t];
    if (b == 0 && t == 0) g_sumnorm = 0.f;
}

// ---------------- kernel 0b: redundant scan + parallel fill (grid NB_) -----
__global__ void __launch_bounds__(512) k0b_fill(const int* __restrict__ label) {
    __shared__ int cur[P_];
    __shared__ int ws[16];
    int t = threadIdx.x, b = blockIdx.x, lane = t & 31, w = t >> 5;

    int pref = 0, tot = 0;
#pragma unroll
    for (int bb = 0; bb < NB_; bb++) {
        int v = g_pc[bb][t];
        if (bb < b) pref += v;
        tot += v;
    }
    int inc = tot;
#pragma unroll
    for (int o = 1; o < 32; o <<= 1) {
        int v = __shfl_up_sync(0xffffffffu, inc, o);
        if (lane >= o) inc += v;
    }
    if (lane == 31) ws[w] = inc;
    __syncthreads();
    if (t < 32) {
        int v = (t < 16) ? ws[t] : 0;
        int s = v;
#pragma unroll
        for (int o = 1; o < 32; o <<= 1) {
            int u = __shfl_up_sync(0xffffffffu, s, o);
            if (lane >= o) s += u;
        }
        if (t < 16) ws[t] = s - v;
    }
    __syncthreads();
    int exc = ws[w] + inc - tot;          // exclusive class prefix
    if (b == 0) { g_count[t] = tot; g_offset[t] = exc; }
    cur[t] = exc + pref;                  // this partition's write base
    __syncthreads();
    int i = b * 512 + t;
    int c = __ldg(&label[i]);
    int pos = atomicAdd(&cur[c], 1);
    g_members[pos] = i;
}

// ---------------- kernel 1: centers via LDGSTS smem ring (proven R7) -------
// grid (P_, 3), block 256. 4-stage ring of full rows (8 KB each, 32 KB smem).
__global__ void __launch_bounds__(256) k1_centers(const float* __restrict__ f0,
                                                  const float* __restrict__ f1,
                                                  const float* __restrict__ f2) {
    int c = blockIdx.x, m = blockIdx.y;
    const float* f = (m == 0) ? f0 : ((m == 1) ? f1 : f2);
    int off = g_offset[c];
    int K   = g_count[c];
    int t   = threadIdx.x, w = t >> 5, lane = t & 31;

    __shared__ __align__(16) float stg[S_][D_];   // 32 KB ring
    __shared__ float wred[2][8];

#pragma unroll
    for (int s = 0; s < S_; s++) {
        if (s < K) {
            int row = __ldg(&g_members[off + s]);
            const float* src = f + (size_t)row * D_;
            cpa16(&stg[s][t * 4], src + t * 4);
            cpa16(&stg[s][1024 + t * 4], src + 1024 + t * 4);
        }
        cpa_commit();
    }

    float a0 = 0.f, a1 = 0.f, a2 = 0.f, a3 = 0.f;
    float a4 = 0.f, a5 = 0.f, a6 = 0.f, a7 = 0.f;

    for (int k = 0; k < K; k++) {
        cpa_wait<S_ - 1>();          // this thread's stage-k copy landed
        int sb = k & (S_ - 1);
        float4 x = *(const float4*)&stg[sb][t * 4];
        float4 y = *(const float4*)&stg[sb][1024 + t * 4];
        int kn = k + S_;             // refill own region (no cross-thread hazard)
        if (kn < K) {
            int row = __ldg(&g_members[off + kn]);
            const float* src = f + (size_t)row * D_;
            cpa16(&stg[sb][t * 4], src + t * 4);
            cpa16(&stg[sb][1024 + t * 4], src + 1024 + t * 4);
        }
        cpa_commit();
        float ss = warpSum(dot8(x, y));
        if (lane == 0) wred[k & 1][w] = ss;
        __syncthreads();             // single barrier per row
        float tot = wred[k & 1][0] + wred[k & 1][1] + wred[k & 1][2] + wred[k & 1][3]
                  + wred[k & 1][4] + wred[k & 1][5] + wred[k & 1][6] + wred[k & 1][7];
        float inv = rsqrtf(fmaxf(tot, 1e-24f));
        a0 += x.x * inv; a1 += x.y * inv; a2 += x.z * inv; a3 += x.w * inv;
        a4 += y.x * inv; a5 += y.y * inv; a6 += y.z * inv; a7 += y.w * inv;
    }

    float ss2 = a0 * a0 + a1 * a1 + a2 * a2 + a3 * a3
              + a4 * a4 + a5 * a5 + a6 * a6 + a7 * a7;
    ss2 = warpSum(ss2);
    __syncthreads();
    if (lane == 0) wred[0][w] = ss2;
    __syncthreads();
    float tot2 = wred[0][0] + wred[0][1] + wred[0][2] + wred[0][3]
               + wred[0][4] + wred[0][5] + wred[0][6] + wred[0][7];
    float nrm  = sqrtf(tot2);
    float inv2 = 1.f / fmaxf(nrm, EPSF);

    __nv_bfloat16* cb = &g_cbf[m][c][0];
    uint2 u0, u1;
    u0.x = bfpack(a0 * inv2, a1 * inv2); u0.y = bfpack(a2 * inv2, a3 * inv2);
    u1.x = bfpack(a4 * inv2, a5 * inv2); u1.y = bfpack(a6 * inv2, a7 * inv2);
    *(uint2*)(cb + 4 * t)         = u0;
    *(uint2*)(cb + 4 * (t + 256)) = u1;
    if (t == 0) atomicAdd(&g_sumnorm, nrm);
}

// ---------------- kernel 2: split-K bf16 mma GEMM --------------------------
// grid (8, 8, 12): z = p*4 + ks. Each block: 64x64 tile over K=512 (8 chunks).
// 768 blocks all co-resident (~5/SM) -> cross-block latency hiding.
// Partials written non-atomically to g_part[p][ks].
#define KC_ 64
__device__ __forceinline__ unsigned sw_off(int row, int g) {
    return (unsigned)(row * 128 + ((g ^ (row & 7)) << 4));
}

__global__ void __launch_bounds__(128) k2_gemm() {
    __shared__ __align__(16) unsigned char As[64 * 128];
    __shared__ __align__(16) unsigned char Bs[64 * 128];
    unsigned asb = (unsigned)__cvta_generic_to_shared(As);
    unsigned bsb = (unsigned)__cvta_generic_to_shared(Bs);

    int z  = blockIdx.z;
    int p  = z >> 2, ks = z & 3;
    int pa = (p == 2) ? 1 : 0;
    int pb = (p == 0) ? 1 : 2;
    const __nv_bfloat16* A = &g_cbf[pa][0][0];
    const __nv_bfloat16* B = &g_cbf[pb][0][0];

    int t = threadIdx.x, lane = t & 31, warp = t >> 5;
    int wr = warp >> 1, wc = warp & 1;
    int brow = blockIdx.y * 64, bcol = blockIdx.x * 64;
    int k0 = ks * 512;

    float acc[2][4][4];
#pragma unroll
    for (int mt = 0; mt < 2; mt++)
#pragma unroll
        for (int nt = 0; nt < 4; nt++)
#pragma unroll
            for (int e = 0; e < 4; e++) acc[mt][nt][e] = 0.f;

    int rsel = lane & 15, gsel = lane >> 4;

    uint4 ga[4], gb[4];
#pragma unroll
    for (int j = 0; j < 4; j++) {
        int i = t + j * 128, row = i >> 3, g = i & 7;
        ga[j] = *(const uint4*)(A + (size_t)(brow + row) * D_ + k0 + g * 8);
        gb[j] = *(const uint4*)(B + (size_t)(bcol + row) * D_ + k0 + g * 8);
    }

    for (int lc = 0; lc < 512 / KC_; lc++) {
#pragma unroll
        for (int j = 0; j < 4; j++) {
            int i = t + j * 128, row = i >> 3, g = i & 7;
            *(uint4*)(As + sw_off(row, g)) = ga[j];
            *(uint4*)(Bs + sw_off(row, g)) = gb[j];
        }
        __syncthreads();

        if (lc + 1 < 512 / KC_) {
            int co = k0 + (lc + 1) * KC_;
#pragma unroll
            for (int j = 0; j < 4; j++) {
                int i = t + j * 128, row = i >> 3, g = i & 7;
                ga[j] = *(const uint4*)(A + (size_t)(brow + row) * D_ + co + g * 8);
                gb[j] = *(const uint4*)(B + (size_t)(bcol + row) * D_ + co + g * 8);
            }
        }

#pragma unroll
        for (int kh = 0; kh < 4; kh++) {
            unsigned af[2][4], bfr[2][4];
#pragma unroll
            for (int mt = 0; mt < 2; mt++) {
                unsigned ad = asb + sw_off(wr * 32 + mt * 16 + rsel, kh * 2 + gsel);
                asm volatile("ldmatrix.sync.aligned.m8n8.x4.shared.b16 {%0,%1,%2,%3}, [%4];"
                             : "=r"(af[mt][0]), "=r"(af[mt][1]), "=r"(af[mt][2]), "=r"(af[mt][3])
                             : "r"(ad));
            }
#pragma unroll
            for (int np = 0; np < 2; np++) {
                unsigned bd = bsb + sw_off(wc * 32 + np * 16 + rsel, kh * 2 + gsel);
                asm volatile("ldmatrix.sync.aligned.m8n8.x4.shared.b16 {%0,%1,%2,%3}, [%4];"
                             : "=r"(bfr[np][0]), "=r"(bfr[np][1]), "=r"(bfr[np][2]), "=r"(bfr[np][3])
                             : "r"(bd));
            }
#pragma unroll
            for (int mt = 0; mt < 2; mt++)
#pragma unroll
                for (int nt = 0; nt < 4; nt++) {
                    int np = nt >> 1, s = nt & 1;
                    asm volatile(
                        "mma.sync.aligned.m16n8k16.row.col.f32.bf16.bf16.f32 "
                        "{%0,%1,%2,%3},{%4,%5,%6,%7},{%8,%9},{%0,%1,%2,%3};"
                        : "+f"(acc[mt][nt][0]), "+f"(acc[mt][nt][1]),
                          "+f"(acc[mt][nt][2]), "+f"(acc[mt][nt][3])
                        : "r"(af[mt][0]), "r"(af[mt][1]), "r"(af[mt][2]), "r"(af[mt][3]),
                          "r"(bfr[np][0 + s]), "r"(bfr[np][2 + s]));
                }
        }
        __syncthreads();
    }

    float* C = &g_part[p][ks][0][0];
#pragma unroll
    for (int mt = 0; mt < 2; mt++)
#pragma unroll
        for (int nt = 0; nt < 4; nt++) {
            int row = brow + wr * 32 + mt * 16 + (lane >> 2);
            int col = bcol + wc * 32 + nt * 8 + (lane & 3) * 2;
            *(float2*)(C + (size_t)row * P_ + col)       = make_float2(acc[mt][nt][0], acc[mt][nt][1]);
            *(float2*)(C + (size_t)(row + 8) * P_ + col) = make_float2(acc[mt][nt][2], acc[mt][nt][3]);
        }
}

// ---------------- kernel 3a: combine splits + exp-sum + diag, warp/row -----
// grid 192, block 256 (8 warps). Logits bounded (|2*dot|<=2): no max shift.
__global__ void __launch_bounds__(256) k3_row() {
    int warp = threadIdx.x >> 5, lane = threadIdx.x & 31;
    int gid = blockIdx.x * 8 + warp;          // 0 .. 1535
    int p = gid >> 9, i = gid & (P_ - 1);
    const float* b0 = &g_part[p][0][i][0];    // plane stride P_*P_

    float es = 0.f, dg = 0.f;
#pragma unroll
    for (int j = 0; j < 4; j++) {
        int c0 = lane * 4 + j * 128;
        float4 v0 = *(const float4*)(b0 + c0);
        float4 v1 = *(const float4*)(b0 + P_ * P_ + c0);
        float4 v2 = *(const float4*)(b0 + 2 * P_ * P_ + c0);
        float4 v3 = *(const float4*)(b0 + 3 * P_ * P_ + c0);
        float sx = v0.x + v1.x + v2.x + v3.x;
        float sy = v0.y + v1.y + v2.y + v3.y;
        float sz = v0.z + v1.z + v2.z + v3.z;
        float sw = v0.w + v1.w + v2.w + v3.w;
        es += __expf(2.f * sx) + __expf(2.f * sy)
            + __expf(2.f * sz) + __expf(2.f * sw);
        if (i == c0)     dg += sx;
        if (i == c0 + 1) dg += sy;
        if (i == c0 + 2) dg += sz;
        if (i == c0 + 3) dg += sw;
    }
    es = warpSum(es);
    dg = warpSum(dg);
    if (lane == 0) g_rowloss[gid] = __logf(es) - 2.f * dg;
}

// ---------------- kernel 3b: final scalar ----------------------------------
__global__ void __launch_bounds__(512) k3_final(float* __restrict__ out) {
    int t = threadIdx.x;  // 512 threads
    float rl = g_rowloss[t] + g_rowloss[t + 512] + g_rowloss[t + 1024];
    __shared__ float w1[16];
    rl = warpSum(rl);
    if ((t & 31) == 0) w1[t >> 5] = rl;
    __syncthreads();
    if (t == 0) {
        float R = 0.f;
        for (int i = 0; i < 16; i++) R += w1[i];
        // loss_intra = 6 - (2/N)*sum||s||;  loss_inter = (sum rowloss)/P
        out[0] = 6.f - g_sumnorm / 4096.f + R / 512.f;
    }
}

// ---------------- launch ----------------------------------------------------
extern "C" void kernel_launch(void* const* d_in, const int* in_sizes, int n_in,
                              void* d_out, int out_size) {
    const float* fv    = (const float*)d_in[0];
    const float* fa    = (const float*)d_in[1];
    const float* fr    = (const float*)d_in[2];
    const int*   label = (const int*)d_in[3];
    (void)in_sizes; (void)n_in; (void)out_size;

    k0a_hist<<<NB_, 512>>>(label);
    k0b_fill<<<NB_, 512>>>(label);
    k1_centers<<<dim3(P_, 3), 256>>>(fv, fa, fr);
    k2_gemm<<<dim3(8, 8, 12), 128>>>();
    k3_row<<<192, 256>>>();
    k3_final<<<1, 512>>>((float*)d_out);
}

// round 13
// speedup vs baseline: 1.1920x; 1.0090x over previous
#include <cuda_runtime.h>
#include <cuda_bf16.h>
#include <math.h>

#define N_   8192
#define D_   2048
#define P_   512
#define NB_  16          // k0 partition blocks (512 samples each)
#define EPSF 1e-12f
#define S_   4           // k1 LDGSTS ring depth (4 x 8KB static smem)

// ---------------- scratch (device globals; no allocation allowed) ----------
__device__ int   g_count[P_];
__device__ int   g_offset[P_];
__device__ int   g_members[N_];
__device__ int   g_pc[NB_][P_];              // per-partition class histograms
__device__ __nv_bfloat16 g_cbf[3][P_][D_];   // unit centers, bf16
__device__ float g_part[3][4][P_][P_];       // split-K partial dot planes (12MB)
__device__ float g_rowloss[3 * P_];
__device__ float g_sumnorm;                  // sum ||s_c|| over all (m, c)

// ---------------- helpers --------------------------------------------------
__device__ __forceinline__ float warpSum(float v) {
#pragma unroll
    for (int o = 16; o; o >>= 1) v += __shfl_xor_sync(0xffffffffu, v, o);
    return v;
}
__device__ __forceinline__ unsigned bfpack(float lo, float hi) {
    unsigned a = (unsigned)__bfloat16_as_ushort(__float2bfloat16_rn(lo));
    unsigned b = (unsigned)__bfloat16_as_ushort(__float2bfloat16_rn(hi));
    return a | (b << 16);
}
__device__ __forceinline__ float dot8(const float4& x, const float4& y) {
    return x.x * x.x + x.y * x.y + x.z * x.z + x.w * x.w
         + y.x * y.x + y.y * y.y + y.z * y.z + y.w * y.w;
}
__device__ __forceinline__ void cpa16(void* dst, const void* src) {
    unsigned d = (unsigned)__cvta_generic_to_shared(dst);
    asm volatile("cp.async.cg.shared.global [%0], [%1], 16;\n" :: "r"(d), "l"(src));
}
__device__ __forceinline__ void cpa_commit() {
    asm volatile("cp.async.commit_group;\n" ::: "memory");
}
template <int Npend>
__device__ __forceinline__ void cpa_wait() {
    asm volatile("cp.async.wait_group %0;\n" :: "n"(Npend) : "memory");
}

// ---------------- kernel 0a: per-partition histogram + zero sumnorm --------
__global__ void __launch_bounds__(512) k0a_hist(const int* __restrict__ label) {
    __shared__ int h[P_];
    int t = threadIdx.x, b = blockIdx.x;
    h[t] = 0;
    __syncthreads();
    int l = __ldg(&label[b * 512 + t]);
    atomicAdd(&h[l], 1);
    __syncthreads();
    g_pc[b][t] = h[t];
    if (b == 0 && t == 0) g_sumnorm = 0.f;
}

// ---------------- kernel 0b: redundant scan + parallel fill (grid NB_) -----
__global__ void __launch_bounds__(512) k0b_fill(const int* __restrict__ label) {
    __shared__ int cur[P_];
    __shared__ int ws[16];
    int t = threadIdx.x, b = blockIdx.x, lane = t & 31, w = t >> 5;

    int pref = 0, tot = 0;
#pragma unroll
    for (int bb = 0; bb < NB_; bb++) {
        int v = g_pc[bb][t];
        if (bb < b) pref += v;
        tot += v;
    }
    int inc = tot;
#pragma unroll
    for (int o = 1; o < 32; o <<= 1) {
        int v = __shfl_up_sync(0xffffffffu, inc, o);
        if (lane >= o) inc += v;
    }
    if (lane == 31) ws[w] = inc;
    __syncthreads();
    if (t < 32) {
        int v = (t < 16) ? ws[t] : 0;
        int s = v;
#pragma unroll
        for (int o = 1; o < 32; o <<= 1) {
            int u = __shfl_up_sync(0xffffffffu, s, o);
            if (lane >= o) s += u;
        }
        if (t < 16) ws[t] = s - v;
    }
    __syncthreads();
    int exc = ws[w] + inc - tot;          // exclusive class prefix
    if (b == 0) { g_count[t] = tot; g_offset[t] = exc; }
    cur[t] = exc + pref;                  // this partition's write base
    __syncthreads();
    int i = b * 512 + t;
    int c = __ldg(&label[i]);
    int pos = atomicAdd(&cur[c], 1);
    g_members[pos] = i;
}

// ---------------- kernel 1: centers via LDGSTS smem ring (proven R7) -------
// grid (P_, 3), block 256. 4-stage ring of full rows (8 KB each, 32 KB smem).
__global__ void __launch_bounds__(256) k1_centers(const float* __restrict__ f0,
                                                  const float* __restrict__ f1,
                                                  const float* __restrict__ f2) {
    int c = blockIdx.x, m = blockIdx.y;
    const float* f = (m == 0) ? f0 : ((m == 1) ? f1 : f2);
    int off = g_offset[c];
    int K   = g_count[c];
    int t   = threadIdx.x, w = t >> 5, lane = t & 31;

    __shared__ __align__(16) float stg[S_][D_];   // 32 KB ring
    __shared__ float wred[2][8];

#pragma unroll
    for (int s = 0; s < S_; s++) {
        if (s < K) {
            int row = __ldg(&g_members[off + s]);
            const float* src = f + (size_t)row * D_;
            cpa16(&stg[s][t * 4], src + t * 4);
            cpa16(&stg[s][1024 + t * 4], src + 1024 + t * 4);
        }
        cpa_commit();
    }

    float a0 = 0.f, a1 = 0.f, a2 = 0.f, a3 = 0.f;
    float a4 = 0.f, a5 = 0.f, a6 = 0.f, a7 = 0.f;

    for (int k = 0; k < K; k++) {
        cpa_wait<S_ - 1>();          // this thread's stage-k copy landed
        int sb = k & (S_ - 1);
        float4 x = *(const float4*)&stg[sb][t * 4];
        float4 y = *(const float4*)&stg[sb][1024 + t * 4];
        int kn = k + S_;             // refill own region (no cross-thread hazard)
        if (kn < K) {
            int row = __ldg(&g_members[off + kn]);
            const float* src = f + (size_t)row * D_;
            cpa16(&stg[sb][t * 4], src + t * 4);
            cpa16(&stg[sb][1024 + t * 4], src + 1024 + t * 4);
        }
        cpa_commit();
        float ss = warpSum(dot8(x, y));
        if (lane == 0) wred[k & 1][w] = ss;
        __syncthreads();             // single barrier per row
        float tot = wred[k & 1][0] + wred[k & 1][1] + wred[k & 1][2] + wred[k & 1][3]
                  + wred[k & 1][4] + wred[k & 1][5] + wred[k & 1][6] + wred[k & 1][7];
        float inv = rsqrtf(fmaxf(tot, 1e-24f));
        a0 += x.x * inv; a1 += x.y * inv; a2 += x.z * inv; a3 += x.w * inv;
        a4 += y.x * inv; a5 += y.y * inv; a6 += y.z * inv; a7 += y.w * inv;
    }

    float ss2 = a0 * a0 + a1 * a1 + a2 * a2 + a3 * a3
              + a4 * a4 + a5 * a5 + a6 * a6 + a7 * a7;
    ss2 = warpSum(ss2);
    __syncthreads();
    if (lane == 0) wred[0][w] = ss2;
    __syncthreads();
    float tot2 = wred[0][0] + wred[0][1] + wred[0][2] + wred[0][3]
               + wred[0][4] + wred[0][5] + wred[0][6] + wred[0][7];
    float nrm  = sqrtf(tot2);
    float inv2 = 1.f / fmaxf(nrm, EPSF);

    __nv_bfloat16* cb = &g_cbf[m][c][0];
    uint2 u0, u1;
    u0.x = bfpack(a0 * inv2, a1 * inv2); u0.y = bfpack(a2 * inv2, a3 * inv2);
    u1.x = bfpack(a4 * inv2, a5 * inv2); u1.y = bfpack(a6 * inv2, a7 * inv2);
    *(uint2*)(cb + 4 * t)         = u0;
    *(uint2*)(cb + 4 * (t + 256)) = u1;
    if (t == 0) atomicAdd(&g_sumnorm, nrm);
}

// ---------------- kernel 2: split-K bf16 mma GEMM, 2-stage cp.async --------
// grid (8, 8, 12): z = p*4 + ks. Each block: 64x64 tile over K=512 (8 chunks).
// 2-stage cp.async staging (32 KB smem) removes the 32-reg prefetch -> lower
// regs -> more resident blocks -> more independent mma chains per SM.
#define KC_ 64
#define NC_ (512 / KC_)
__device__ __forceinline__ unsigned sw_off(int row, int g) {
    return (unsigned)(row * 128 + ((g ^ (row & 7)) << 4));
}

__global__ void __launch_bounds__(128) k2_gemm() {
    __shared__ __align__(16) unsigned char As[2][64 * 128];
    __shared__ __align__(16) unsigned char Bs[2][64 * 128];

    int z  = blockIdx.z;
    int p  = z >> 2, ks = z & 3;
    int pa = (p == 2) ? 1 : 0;
    int pb = (p == 0) ? 1 : 2;
    const __nv_bfloat16* A = &g_cbf[pa][0][0];
    const __nv_bfloat16* B = &g_cbf[pb][0][0];

    int t = threadIdx.x, lane = t & 31, warp = t >> 5;
    int wr = warp >> 1, wc = warp & 1;
    int brow = blockIdx.y * 64, bcol = blockIdx.x * 64;
    int k0 = ks * 512;

    float acc[2][4][4];
#pragma unroll
    for (int mt = 0; mt < 2; mt++)
#pragma unroll
        for (int nt = 0; nt < 4; nt++)
#pragma unroll
            for (int e = 0; e < 4; e++) acc[mt][nt][e] = 0.f;

    int rsel = lane & 15, gsel = lane >> 4;
    int lrow = t >> 3 << 2, lg = t & 7;   // unused helper (kept simple below)

    // loader mapping: i = t + j*128 -> row = i>>3, g = i&7 (64 rows x 8 granules)
    // prologue: chunk 0 -> stage 0
#pragma unroll
    for (int j = 0; j < 4; j++) {
        int i = t + j * 128, row = i >> 3, g = i & 7;
        cpa16(&As[0][sw_off(row, g)], A + (size_t)(brow + row) * D_ + k0 + g * 8);
        cpa16(&Bs[0][sw_off(row, g)], B + (size_t)(bcol + row) * D_ + k0 + g * 8);
    }
    cpa_commit();

    for (int lc = 0; lc < NC_; lc++) {
        int st = lc & 1;
        if (lc + 1 < NC_) {        // prefetch chunk lc+1 into the other stage
            int co = k0 + (lc + 1) * KC_;
            int ns = st ^ 1;
#pragma unroll
            for (int j = 0; j < 4; j++) {
                int i = t + j * 128, row = i >> 3, g = i & 7;
                cpa16(&As[ns][sw_off(row, g)], A + (size_t)(brow + row) * D_ + co + g * 8);
                cpa16(&Bs[ns][sw_off(row, g)], B + (size_t)(bcol + row) * D_ + co + g * 8);
            }
            cpa_commit();
            cpa_wait<1>();         // chunk lc done; lc+1 still in flight
        } else {
            cpa_wait<0>();         // final chunk done
        }
        __syncthreads();           // chunk lc visible to all threads

        unsigned ab = (unsigned)__cvta_generic_to_shared(&As[st][0]);
        unsigned bb = (unsigned)__cvta_generic_to_shared(&Bs[st][0]);
#pragma unroll
        for (int kh = 0; kh < 4; kh++) {
            unsigned af[2][4], bfr[2][4];
#pragma unroll
            for (int mt = 0; mt < 2; mt++) {
                unsigned ad = ab + sw_off(wr * 32 + mt * 16 + rsel, kh * 2 + gsel);
                asm volatile("ldmatrix.sync.aligned.m8n8.x4.shared.b16 {%0,%1,%2,%3}, [%4];"
                             : "=r"(af[mt][0]), "=r"(af[mt][1]), "=r"(af[mt][2]), "=r"(af[mt][3])
                             : "r"(ad));
            }
#pragma unroll
            for (int np = 0; np < 2; np++) {
                unsigned bd = bb + sw_off(wc * 32 + np * 16 + rsel, kh * 2 + gsel);
                asm volatile("ldmatrix.sync.aligned.m8n8.x4.shared.b16 {%0,%1,%2,%3}, [%4];"
                             : "=r"(bfr[np][0]), "=r"(bfr[np][1]), "=r"(bfr[np][2]), "=r"(bfr[np][3])
                             : "r"(bd));
            }
#pragma unroll
            for (int mt = 0; mt < 2; mt++)
#pragma unroll
                for (int nt = 0; nt < 4; nt++) {
                    int np = nt >> 1, s = nt & 1;
                    asm volatile(
                        "mma.sync.aligned.m16n8k16.row.col.f32.bf16.bf16.f32 "
                        "{%0,%1,%2,%3},{%4,%5,%6,%7},{%8,%9},{%0,%1,%2,%3};"
                        : "+f"(acc[mt][nt][0]), "+f"(acc[mt][nt][1]),
                          "+f"(acc[mt][nt][2]), "+f"(acc[mt][nt][3])
                        : "r"(af[mt][0]), "r"(af[mt][1]), "r"(af[mt][2]), "r"(af[mt][3]),
                          "r"(bfr[np][0 + s]), "r"(bfr[np][2 + s]));
                }
        }
        __syncthreads();           // stage st free before iter lc+1 overwrites it
    }

    float* C = &g_part[p][ks][0][0];
#pragma unroll
    for (int mt = 0; mt < 2; mt++)
#pragma unroll
        for (int nt = 0; nt < 4; nt++) {
            int row = brow + wr * 32 + mt * 16 + (lane >> 2);
            int col = bcol + wc * 32 + nt * 8 + (lane & 3) * 2;
            *(float2*)(C + (size_t)row * P_ + col)       = make_float2(acc[mt][nt][0], acc[mt][nt][1]);
            *(float2*)(C + (size_t)(row + 8) * P_ + col) = make_float2(acc[mt][nt][2], acc[mt][nt][3]);
        }
}

// ---------------- kernel 3a: combine splits + exp-sum + diag, warp/row -----
// grid 192, block 256 (8 warps). Logits bounded (|2*dot|<=2): no max shift.
__global__ void __launch_bounds__(256) k3_row() {
    int warp = threadIdx.x >> 5, lane = threadIdx.x & 31;
    int gid = blockIdx.x * 8 + warp;          // 0 .. 1535
    int p = gid >> 9, i = gid & (P_ - 1);
    const float* b0 = &g_part[p][0][i][0];    // plane stride P_*P_

    float es = 0.f, dg = 0.f;
#pragma unroll
    for (int j = 0; j < 4; j++) {
        int c0 = lane * 4 + j * 128;
        float4 v0 = *(const float4*)(b0 + c0);
        float4 v1 = *(const float4*)(b0 + P_ * P_ + c0);
        float4 v2 = *(const float4*)(b0 + 2 * P_ * P_ + c0);
        float4 v3 = *(const float4*)(b0 + 3 * P_ * P_ + c0);
        float sx = v0.x + v1.x + v2.x + v3.x;
        float sy = v0.y + v1.y + v2.y + v3.y;
        float sz = v0.z + v1.z + v2.z + v3.z;
        float sw = v0.w + v1.w + v2.w + v3.w;
        es += __expf(2.f * sx) + __expf(2.f * sy)
            + __expf(2.f * sz) + __expf(2.f * sw);
        if (i == c0)     dg += sx;
        if (i == c0 + 1) dg += sy;
        if (i == c0 + 2) dg += sz;
        if (i == c0 + 3) dg += sw;
    }
    es = warpSum(es);
    dg = warpSum(dg);
    if (lane == 0) g_rowloss[gid] = __logf(es) - 2.f * dg;
}

// ---------------- kernel 3b: final scalar ----------------------------------
__global__ void __launch_bounds__(512) k3_final(float* __restrict__ out) {
    int t = threadIdx.x;  // 512 threads
    float rl = g_rowloss[t] + g_rowloss[t + 512] + g_rowloss[t + 1024];
    __shared__ float w1[16];
    rl = warpSum(rl);
    if ((t & 31) == 0) w1[t >> 5] = rl;
    __syncthreads();
    if (t == 0) {
        float R = 0.f;
        for (int i = 0; i < 16; i++) R += w1[i];
        // loss_intra = 6 - (2/N)*sum||s||;  loss_inter = (sum rowloss)/P
        out[0] = 6.f - g_sumnorm / 4096.f + R / 512.f;
    }
}

// ---------------- launch ----------------------------------------------------
extern "C" void kernel_launch(void* const* d_in, const int* in_sizes, int n_in,
                              void* d_out, int out_size) {
    const float* fv    = (const float*)d_in[0];
    const float* fa    = (const float*)d_in[1];
    const float* fr    = (const float*)d_in[2];
    const int*   label = (const int*)d_in[3];
    (void)in_sizes; (void)n_in; (void)out_size;

    k0a_hist<<<NB_, 512>>>(label);
    k0b_fill<<<NB_, 512>>>(label);
    k1_centers<<<dim3(P_, 3), 256>>>(fv, fa, fr);
    k2_gemm<<<dim3(8, 8, 12), 128>>>();
    k3_row<<<192, 256>>>();
    k3_final<<<1, 512>>>((float*)d_out);
}